// round 16
// baseline (speedup 1.0000x reference)
#include <cuda_runtime.h>
#include <cuda_fp16.h>
#include <cstdint>
#include <math.h>

// Problem constants
#define BB   16
#define SS   512
#define DD   512
#define HH   8
#define DK   64
#define DFFN 2048
#define MROWS (BB*SS)   // 8192

// ---------------- scratch (static device globals; no allocation) ----------------
__device__ float g_ao [MROWS*DD];
__device__ float g_x1 [MROWS*DD];
__device__ float g_f2 [MROWS*DD];
__device__ __half g_in16q[MROWS*DD];
__device__ __half g_in16k[MROWS*DD];
__device__ __half g_in16v[MROWS*DD];
__device__ __half g_qh  [MROWS*DD];
__device__ __half g_kh  [MROWS*DD];
__device__ __half g_vh  [MROWS*DD];
__device__ __half g_ctx16[MROWS*DD];
__device__ __half g_x116 [MROWS*DD];
__device__ __half g_h116 [MROWS*DFFN];
__device__ __half g_wkT16[DD*DD];
__device__ __half g_wvT16[DD*DD];
__device__ __half g_woT16[DD*DD];
__device__ __half g_w1T16[DFFN*DD];
__device__ __half g_w2T16[DD*DFFN];

// ---------------- helpers ----------------
__device__ __forceinline__ uint32_t smem_to_u32(const void* p) {
    uint32_t a;
    asm("{ .reg .u64 tmp; cvta.to.shared.u64 tmp, %1; cvt.u32.u64 %0, tmp; }" : "=r"(a) : "l"(p));
    return a;
}
#define CP_ASYNC16(saddr, gptr) \
    asm volatile("cp.async.cg.shared.global [%0], [%1], 16;" :: "r"(saddr), "l"(gptr))
#define CP_COMMIT() asm volatile("cp.async.commit_group;" ::: "memory")
#define CP_WAIT0()  asm volatile("cp.async.wait_group 0;" ::: "memory")
#define CP_WAIT1()  asm volatile("cp.async.wait_group 1;" ::: "memory")

__device__ __forceinline__ void mma_f16(float* c, const uint32_t* a, const uint32_t* b) {
    asm volatile(
        "mma.sync.aligned.m16n8k16.row.col.f32.f16.f16.f32 "
        "{%0,%1,%2,%3}, {%4,%5,%6,%7}, {%8,%9}, {%0,%1,%2,%3};"
        : "+f"(c[0]), "+f"(c[1]), "+f"(c[2]), "+f"(c[3])
        : "r"(a[0]), "r"(a[1]), "r"(a[2]), "r"(a[3]), "r"(b[0]), "r"(b[1]));
}
__device__ __forceinline__ void ldmx4(uint32_t* r, uint32_t addr) {
    asm volatile("ldmatrix.sync.aligned.m8n8.x4.shared.b16 {%0,%1,%2,%3}, [%4];"
                 : "=r"(r[0]), "=r"(r[1]), "=r"(r[2]), "=r"(r[3]) : "r"(addr));
}
__device__ __forceinline__ void ldmx2_trans(uint32_t& r0, uint32_t& r1, uint32_t addr) {
    asm volatile("ldmatrix.sync.aligned.m8n8.x2.trans.shared.b16 {%0,%1}, [%2];"
                 : "=r"(r0), "=r"(r1) : "r"(addr));
}

__device__ __forceinline__ float fexp(float x) {
    float y;
    asm("ex2.approx.f32 %0, %1;" : "=f"(y) : "f"(x * 1.4426950408889634f));
    return y;
}
__device__ __forceinline__ float fsqrt_ap(float x) {
    float y;
    asm("sqrt.approx.f32 %0, %1;" : "=f"(y) : "f"(x));
    return y;
}

// ========================= fp16 mma GEMM: 128x64 tile, 128 thr, 4 CTA/SM =========================
#define HP 72
#define ATILE_H (128*HP)
#define BTILE_H (64*HP)
#define STG_H (ATILE_H + BTILE_H)
#define GEMM_H_SMEM (2*STG_H*(int)sizeof(__half))    // 55,296 B; 4 CTAs = 221,184 <= 228KB

__device__ __forceinline__ void fill_h(const __half* __restrict__ A,
                                       const __half* __restrict__ Bt,
                                       int K, int bm, int bn, int kc,
                                       uint32_t sA, uint32_t sB, int t)
{
    // A: 128 rows x 64 halves = 1024 16B-chunks; 128 threads -> 8 iters
#pragma unroll
    for (int i = 0; i < 8; i++) {
        int id = t + i * 128;
        int row = id >> 3, c = id & 7;
        CP_ASYNC16(sA + (uint32_t)(row * HP + c * 8) * 2u,
                   A + (size_t)(bm + row) * K + kc * 64 + c * 8);
    }
    // B: 64 rows -> 512 chunks -> 4 iters
#pragma unroll
    for (int i = 0; i < 4; i++) {
        int id = t + i * 128;
        int row = id >> 3, c = id & 7;
        CP_ASYNC16(sB + (uint32_t)(row * HP + c * 8) * 2u,
                   Bt + (size_t)(bn + row) * K + kc * 64 + c * 8);
    }
}

template<bool RELU, bool OUT16>
__device__ __forceinline__ void gemm_h_body(const __half* __restrict__ A,
                                            const __half* __restrict__ Bt,
                                            const float* __restrict__ bias,
                                            float* __restrict__ C,
                                            __half* __restrict__ C16,
                                            int N, int K, int bm, int bn,
                                            __half* smem_h)
{
    const int t    = threadIdx.x;
    const int lane = t & 31, wid = t >> 5;       // 4 warps
    const int g    = lane >> 2, tg = lane & 3;
    const int wm   = (wid >> 1) * 64;            // 0 or 64
    const int wn   = (wid & 1) * 32;             // 0 or 32
    const int r8   = lane & 7, quad = lane >> 3;
    const int rowA = (quad & 1) * 8 + r8, colA = (quad >> 1) * 8;
    const int rowB = (quad >> 1) * 8 + r8, colB = (quad & 1) * 8;
    const uint32_t sbase = smem_to_u32(smem_h);

    float acc[4][4][4];
#pragma unroll
    for (int mt = 0; mt < 4; mt++)
#pragma unroll
        for (int nt = 0; nt < 4; nt++)
#pragma unroll
            for (int r = 0; r < 4; r++) acc[mt][nt][r] = 0.f;

    const int nk = K >> 6;

    fill_h(A, Bt, K, bm, bn, 0, sbase, sbase + ATILE_H * 2, t);
    CP_COMMIT();

    for (int kc = 0; kc < nk; kc++) {
        CP_WAIT0();
        __syncthreads();
        if (kc + 1 < nk) {
            const uint32_t off = ((kc + 1) & 1) * (uint32_t)(STG_H * 2);
            fill_h(A, Bt, K, bm, bn, kc + 1, sbase + off, sbase + off + ATILE_H * 2, t);
            CP_COMMIT();
        }
        const uint32_t aSa = sbase + (uint32_t)((kc & 1) * STG_H) * 2u;
        const uint32_t bSa = aSa + (uint32_t)ATILE_H * 2u;

#pragma unroll
        for (int ks = 0; ks < 4; ks++) {
            const int k0 = ks * 16;
            uint32_t bf[4][2];
#pragma unroll
            for (int nh = 0; nh < 2; nh++) {
                uint32_t b4[4];
                ldmx4(b4, bSa + (uint32_t)((wn + nh * 16 + rowB) * HP + k0 + colB) * 2u);
                bf[2*nh  ][0] = b4[0]; bf[2*nh  ][1] = b4[1];
                bf[2*nh+1][0] = b4[2]; bf[2*nh+1][1] = b4[3];
            }
            uint32_t af[4][4];
#pragma unroll
            for (int mt = 0; mt < 4; mt++)
                ldmx4(af[mt], aSa + (uint32_t)((wm + mt * 16 + rowA) * HP + k0 + colA) * 2u);
#pragma unroll
            for (int mt = 0; mt < 4; mt++)
#pragma unroll
                for (int nt = 0; nt < 4; nt++)
                    mma_f16(acc[mt][nt], af[mt], bf[nt]);
        }
    }

#pragma unroll
    for (int mt = 0; mt < 4; mt++) {
#pragma unroll
        for (int nt = 0; nt < 4; nt++) {
            const int row0 = bm + wm + mt * 16 + g;
            const int col  = bn + wn + nt * 8 + 2 * tg;
            float b0 = bias[col], b1 = bias[col + 1];
            float v0 = acc[mt][nt][0] + b0, v1 = acc[mt][nt][1] + b1;
            float v2 = acc[mt][nt][2] + b0, v3 = acc[mt][nt][3] + b1;
            if (RELU) {
                v0 = fmaxf(v0, 0.f); v1 = fmaxf(v1, 0.f);
                v2 = fmaxf(v2, 0.f); v3 = fmaxf(v3, 0.f);
            }
            if (OUT16) {
                *(__half2*)(C16 + (size_t)row0 * N + col)       = __floats2half2_rn(v0, v1);
                *(__half2*)(C16 + (size_t)(row0 + 8) * N + col) = __floats2half2_rn(v2, v3);
            } else {
                *(float2*)(C + (size_t)row0 * N + col)       = make_float2(v0, v1);
                *(float2*)(C + (size_t)(row0 + 8) * N + col) = make_float2(v2, v3);
            }
        }
    }
}

template<bool RELU, bool OUT16>
__global__ __launch_bounds__(128, 4)
void gemm_h(const __half* __restrict__ A, const __half* __restrict__ Bt,
            const float* __restrict__ bias, float* __restrict__ C,
            __half* __restrict__ C16, int M, int N, int K)
{
    extern __shared__ __align__(16) __half smem_h[];
    gemm_h_body<RELU, OUT16>(A, Bt, bias, C, C16, N, K,
                             blockIdx.y * 128, blockIdx.x * 64, smem_h);
}

__global__ __launch_bounds__(128, 4)
void gemm_proj3_h(const __half* __restrict__ A0, const __half* __restrict__ A1,
                  const __half* __restrict__ A2,
                  const __half* __restrict__ WkT, const __half* __restrict__ WvT,
                  const float* __restrict__ bk, const float* __restrict__ bv,
                  __half* __restrict__ C0, __half* __restrict__ C1, __half* __restrict__ C2)
{
    extern __shared__ __align__(16) __half smem_h[];
    const int z = blockIdx.z;
    const __half* A = (z == 0) ? A0 : (z == 1) ? A1 : A2;
    const __half* W = (z == 2) ? WvT : WkT;
    const float* bias = (z == 2) ? bv : bk;
    __half* C16 = (z == 0) ? C0 : (z == 1) ? C1 : C2;
    gemm_h_body<false, true>(A, W, bias, ((float*)0), C16, DD, DD,
                             blockIdx.y * 128, blockIdx.x * 64, smem_h);
}

// ---------------- single merged prep kernel ----------------
__global__ __launch_bounds__(256)
void prep_all(const float* __restrict__ s0, const float* __restrict__ s1,
              const float* __restrict__ s2,
              __half* __restrict__ d0, __half* __restrict__ d1, __half* __restrict__ d2,
              const float* __restrict__ Wk, const float* __restrict__ Wv,
              const float* __restrict__ Wo, const float* __restrict__ W1,
              const float* __restrict__ W2,
              __half* __restrict__ o0, __half* __restrict__ o1,
              __half* __restrict__ o2, __half* __restrict__ o3,
              __half* __restrict__ o4)
{
    const int z = blockIdx.z;
    if (z < 3) {
        const float* s = (z == 0) ? s0 : (z == 1) ? s1 : s2;
        __half* d = (z == 0) ? d0 : (z == 1) ? d1 : d2;
        const int blk = blockIdx.y * 64 + blockIdx.x;
        const int i = blk * 256 + threadIdx.x;
        float4 v = ((const float4*)s)[i];
        ((__half2*)d)[2 * i    ] = __floats2half2_rn(v.x, v.y);
        ((__half2*)d)[2 * i + 1] = __floats2half2_rn(v.z, v.w);
        return;
    }
    const float* in; __half* out; int R, C;
    switch (z) {
        case 3: in = Wk; out = o0; R = DD;   C = DD;   break;
        case 4: in = Wv; out = o1; R = DD;   C = DD;   break;
        case 5: in = Wo; out = o2; R = DD;   C = DD;   break;
        case 6: in = W1; out = o3; R = DD;   C = DFFN; break;
        default:in = W2; out = o4; R = DFFN; C = DD;   break;
    }
    const int bx = blockIdx.x * 32;
    const int by = blockIdx.y * 32;
    if (bx >= C || by >= R) return;
    __shared__ float tile[32][33];
    const int tx = threadIdx.x & 31;
    const int ty = threadIdx.x >> 5;
#pragma unroll
    for (int i = 0; i < 32; i += 8)
        tile[ty + i][tx] = in[(size_t)(by + ty + i) * C + bx + tx];
    __syncthreads();
#pragma unroll
    for (int i = 0; i < 32; i += 8)
        out[(size_t)(bx + ty + i) * R + by + tx] = __float2half(tile[tx][ty + i]);
}

// ========================= Fused AKT attention: TQ=32, 512 thr, fp16 scores =========================
#define TQ   32
#define CH   128
#define PP   520
#define QP   72
#define KVP  72
#define KVBUF (128*KVP)
#define OFF_Q   33280
#define OFF_KV  (33280+4608)
#define ATTN_SMEM (33280+4608+36864)     // 74,752 B -> 2 CTAs/SM

template<int NCH>
__device__ __forceinline__ void phase_b(__half* sRawH, int w, int lane,
                                        int i0, float gamma)
{
    constexpr int VN = 4 * NCH;
#pragma unroll
    for (int rr2 = 0; rr2 < 2; rr2++) {
        const int row_i = w + rr2 * 16;
        const int ig = i0 + row_i;
        const uint32_t* rp = (const uint32_t*)(sRawH + row_i * PP) + lane * (VN / 2);

        float vals[VN];
#pragma unroll
        for (int u = 0; u < VN / 2; u++) {
            float2 f2 = __half22float2(*(const __half2*)(rp + u));
            vals[2*u] = f2.x; vals[2*u+1] = f2.y;
        }

        float mx = -1e32f;
#pragma unroll
        for (int m = 0; m < VN; m++) mx = fmaxf(mx, vals[m]);
#pragma unroll
        for (int off = 16; off > 0; off >>= 1) mx = fmaxf(mx, __shfl_xor_sync(0xffffffffu, mx, off));

        float p[VN]; float s = 0.f;
#pragma unroll
        for (int m = 0; m < VN; m++) { p[m] = fexp(vals[m] - mx); s += p[m]; }
#pragma unroll
        for (int off = 16; off > 0; off >>= 1) s += __shfl_xor_sync(0xffffffffu, s, off);
        const float inv = 1.f / s;

        float local = 0.f; float cum[VN];
#pragma unroll
        for (int m = 0; m < VN; m++) { local += p[m] * inv; cum[m] = local; }
        float run = local;
#pragma unroll
        for (int off = 1; off < 32; off <<= 1) {
            float vv = __shfl_up_sync(0xffffffffu, run, off);
            if (lane >= off) run += vv;
        }
        const float prefix = run - local;
        const float total  = __shfl_sync(0xffffffffu, run, 31);

#pragma unroll
        for (int m = 0; m < VN; m++) {
            int jg = lane * VN + m;
            float suffix = fmaxf(total - (prefix + cum[m]), 0.f);
            float pe = fabsf((float)(ig - jg));
            float dist = fsqrt_ap(suffix * pe);
            float eff = fexp(dist * gamma);
            eff = fminf(fmaxf(eff, 1e-5f), 1e5f);
            vals[m] = vals[m] * eff;
        }

        float mx2 = -1e32f;
#pragma unroll
        for (int m = 0; m < VN; m++) mx2 = fmaxf(mx2, vals[m]);
#pragma unroll
        for (int off = 16; off > 0; off >>= 1) mx2 = fmaxf(mx2, __shfl_xor_sync(0xffffffffu, mx2, off));
        float s2 = 0.f;
#pragma unroll
        for (int m = 0; m < VN; m++) { vals[m] = fexp(vals[m] - mx2); s2 += vals[m]; }
#pragma unroll
        for (int off = 16; off > 0; off >>= 1) s2 += __shfl_xor_sync(0xffffffffu, s2, off);
        const float inv2 = 1.f / s2;

        uint32_t* wp = (uint32_t*)(sRawH + row_i * PP) + lane * (VN / 2);
#pragma unroll
        for (int u = 0; u < VN / 2; u++) {
            __half2 hv = __floats2half2_rn(vals[2*u] * inv2, vals[2*u+1] * inv2);
            *(__half2*)(wp + u) = hv;
        }
    }
}

__global__ __launch_bounds__(512, 2)
void attn_mma(const __half* __restrict__ Q, const __half* __restrict__ K,
              const __half* __restrict__ V, const float* __restrict__ gammas,
              __half* __restrict__ CTX16)
{
    extern __shared__ __align__(16) char smem_c[];
    __half* sRawH = (__half*)smem_c;
    __half* sQ    = (__half*)(smem_c + OFF_Q);
    __half* sKV   = (__half*)(smem_c + OFF_KV);
    const uint32_t sRa  = smem_to_u32(sRawH);
    const uint32_t sQa  = smem_to_u32(sQ);
    const uint32_t sKVa = smem_to_u32(sKV);

    const int t    = threadIdx.x;
    const int lane = t & 31, w = t >> 5;
    const int g    = lane >> 2, tg = lane & 3;
    const int r8   = lane & 7, quad = lane >> 3;
    const int rowA = (quad & 1) * 8 + r8, colA = (quad >> 1) * 8;
    const int rowB = (quad >> 1) * 8 + r8, colB = (quad & 1) * 8;
    const int qt = (int)(gridDim.x - 1 - blockIdx.x);
    const int h = blockIdx.y, b = blockIdx.z;
    const int i0 = qt * TQ;
    const int nch = (i0 + TQ + CH - 1) >> 7;

    if (t < 256) {
        int r = t >> 3, c8 = t & 7;
        CP_ASYNC16(sQa + (uint32_t)(r * QP + c8 * 8) * 2u,
                   Q + (size_t)(b * SS + i0 + r) * DD + h * 64 + c8 * 8);
    }
    CP_COMMIT();
    {
        const __half* Kb = K + (size_t)(b * SS) * DD + h * 64;
#pragma unroll
        for (int i = 0; i < 2; i++) {
            int id = t + i * 512;
            int r = id >> 3, c8 = id & 7;
            CP_ASYNC16(sKVa + (uint32_t)(r * KVP + c8 * 8) * 2u,
                       Kb + (size_t)r * DD + c8 * 8);
        }
    }
    CP_COMMIT();

    const int rgA = w >> 3;
    const int jsl = (w & 7) * 16;

    CP_WAIT1();
    __syncthreads();
    uint32_t qf[4][4];
#pragma unroll
    for (int ks = 0; ks < 4; ks++)
        ldmx4(qf[ks], sQa + (uint32_t)((rgA * 16 + rowA) * QP + ks * 16 + colA) * 2u);

    const int imax_rg = i0 + rgA * 16 + 15;
    for (int c = 0; c < nch; c++) {
        CP_WAIT0();
        __syncthreads();
        if (c + 1 < nch) {
            const __half* Kb = K + (size_t)(b * SS + (c + 1) * CH) * DD + h * 64;
            const uint32_t dst = sKVa + (uint32_t)(((c + 1) & 1) * KVBUF) * 2u;
#pragma unroll
            for (int i = 0; i < 2; i++) {
                int id = t + i * 512;
                int r = id >> 3, c8 = id & 7;
                CP_ASYNC16(dst + (uint32_t)(r * KVP + c8 * 8) * 2u,
                           Kb + (size_t)r * DD + c8 * 8);
            }
            CP_COMMIT();
        }

        const int rr = rgA * 16 + g;
        if (c * CH + jsl > imax_rg) {
            const __half2 ninf = __floats2half2_rn(-1e30f, -1e30f);
#pragma unroll
            for (int nt = 0; nt < 2; nt++) {
                const int j = c * CH + jsl + nt * 8 + 2 * tg;
                *(__half2*)(sRawH + (rr    ) * PP + j) = ninf;
                *(__half2*)(sRawH + (rr + 8) * PP + j) = ninf;
            }
            continue;
        }

        const uint32_t kba = sKVa + (uint32_t)((c & 1) * KVBUF) * 2u;
        float acc[2][4] = {{0.f,0.f,0.f,0.f},{0.f,0.f,0.f,0.f}};
#pragma unroll
        for (int ks = 0; ks < 4; ks++) {
            uint32_t b4[4];
            ldmx4(b4, kba + (uint32_t)((jsl + rowB) * KVP + ks * 16 + colB) * 2u);
            mma_f16(acc[0], qf[ks], b4 + 0);
            mma_f16(acc[1], qf[ks], b4 + 2);
        }
        const int ilo = i0 + rr, ihi = i0 + rr + 8;
#pragma unroll
        for (int nt = 0; nt < 2; nt++) {
            const int j = c * CH + jsl + nt * 8 + 2 * tg;
            float v0 = (j     <= ilo) ? acc[nt][0] * 0.125f : -1e30f;
            float v1 = (j + 1 <= ilo) ? acc[nt][1] * 0.125f : -1e30f;
            float v2 = (j     <= ihi) ? acc[nt][2] * 0.125f : -1e30f;
            float v3 = (j + 1 <= ihi) ? acc[nt][3] * 0.125f : -1e30f;
            *(__half2*)(sRawH + (rr    ) * PP + j) = __floats2half2_rn(v0, v1);
            *(__half2*)(sRawH + (rr + 8) * PP + j) = __floats2half2_rn(v2, v3);
        }
    }
    __syncthreads();

    {
        const __half* Vb = V + (size_t)(b * SS) * DD + h * 64;
#pragma unroll
        for (int i = 0; i < 2; i++) {
            int id = t + i * 512;
            int r = id >> 3, c8 = id & 7;
            CP_ASYNC16(sKVa + (uint32_t)(r * KVP + c8 * 8) * 2u,
                       Vb + (size_t)r * DD + c8 * 8);
        }
    }
    CP_COMMIT();

    {
        float gm  = gammas[h];
        float sp  = (gm > 20.f) ? gm : log1pf(expf(gm));
        float gamma = -sp;
        switch (nch) {
            case 1:  phase_b<1>(sRawH, w, lane, i0, gamma); break;
            case 2:  phase_b<2>(sRawH, w, lane, i0, gamma); break;
            case 3:  phase_b<3>(sRawH, w, lane, i0, gamma); break;
            default: phase_b<4>(sRawH, w, lane, i0, gamma); break;
        }
    }
    __syncthreads();

    float oc[4] = {0.f, 0.f, 0.f, 0.f};
    const int rgC  = w >> 3;
    const int dcol = (w & 7) * 8;
    const int lrow = lane & 15;
    const int jlim = i0 + TQ;
    for (int c = 0; c < nch; c++) {
        CP_WAIT0();
        __syncthreads();
        if (c + 1 < nch) {
            const __half* Vb = V + (size_t)(b * SS + (c + 1) * CH) * DD + h * 64;
            const uint32_t dst = sKVa + (uint32_t)(((c + 1) & 1) * KVBUF) * 2u;
#pragma unroll
            for (int i = 0; i < 2; i++) {
                int id = t + i * 512;
                int r = id >> 3, c8 = id & 7;
                CP_ASYNC16(dst + (uint32_t)(r * KVP + c8 * 8) * 2u,
                           Vb + (size_t)r * DD + c8 * 8);
            }
            CP_COMMIT();
        }
        const uint32_t vba = sKVa + (uint32_t)((c & 1) * KVBUF) * 2u;

        const int kmax = (jlim - c * CH < CH) ? (jlim - c * CH) : CH;
        for (int kk = 0; kk < kmax; kk += 16) {
            const int jcol = c * CH + kk;
            uint32_t af[4];
            ldmx4(af, sRa + (uint32_t)((rgC * 16 + rowA) * PP + jcol + colA) * 2u);
            uint32_t bf[2];
            ldmx2_trans(bf[0], bf[1],
                        vba + (uint32_t)((kk + lrow) * KVP + dcol) * 2u);
            mma_f16(oc, af, bf);
        }
    }

    const int row0 = i0 + rgC * 16 + g;
    const int col  = h * 64 + dcol + 2 * tg;
    *(__half2*)(CTX16 + (size_t)(b * SS + row0    ) * DD + col) = __floats2half2_rn(oc[0], oc[1]);
    *(__half2*)(CTX16 + (size_t)(b * SS + row0 + 8) * DD + col) = __floats2half2_rn(oc[2], oc[3]);
}

// ---------------- residual add + LayerNorm: warp per row ----------------
__global__ __launch_bounds__(256)
void add_ln(const float* __restrict__ A, const float* __restrict__ B,
            const float* __restrict__ g, const float* __restrict__ be,
            float* __restrict__ O, __half* __restrict__ O16)
{
    const int lane = threadIdx.x & 31;
    const int row  = blockIdx.x * 8 + (threadIdx.x >> 5);
    const float4* a4 = (const float4*)(A + (size_t)row * DD);
    const float4* b4 = (const float4*)(B + (size_t)row * DD);
    const float4* g4 = (const float4*)g;
    const float4* e4 = (const float4*)be;

    float4 x[4];
    float s = 0.f, sq = 0.f;
#pragma unroll
    for (int u = 0; u < 4; u++) {
        const int idx = lane + 32 * u;
        float4 av = a4[idx], bv = b4[idx];
        x[u].x = av.x + bv.x; x[u].y = av.y + bv.y;
        x[u].z = av.z + bv.z; x[u].w = av.w + bv.w;
        s  += x[u].x + x[u].y + x[u].z + x[u].w;
        sq += x[u].x * x[u].x + x[u].y * x[u].y + x[u].z * x[u].z + x[u].w * x[u].w;
    }
#pragma unroll
    for (int off = 16; off > 0; off >>= 1) {
        s  += __shfl_xor_sync(0xffffffffu, s, off);
        sq += __shfl_xor_sync(0xffffffffu, sq, off);
    }
    const float mu   = s * (1.f / 512.f);
    const float var  = fmaxf(sq * (1.f / 512.f) - mu * mu, 0.f);
    const float rstd = rsqrtf(var + 1e-5f);

    float4* o4 = (float4*)(O + (size_t)row * DD);
#pragma unroll
    for (int u = 0; u < 4; u++) {
        const int idx = lane + 32 * u;
        float4 gv = g4[idx], ev = e4[idx];
        float4 y;
        y.x = (x[u].x - mu) * rstd * gv.x + ev.x;
        y.y = (x[u].y - mu) * rstd * gv.y + ev.y;
        y.z = (x[u].z - mu) * rstd * gv.z + ev.z;
        y.w = (x[u].w - mu) * rstd * gv.w + ev.w;
        o4[idx] = y;
        if (O16) {
            __half2* h2 = (__half2*)(O16 + (size_t)row * DD + idx * 4);
            h2[0] = __floats2half2_rn(y.x, y.y);
            h2[1] = __floats2half2_rn(y.z, y.w);
        }
    }
}

// ---------------- launch ----------------
extern "C" void kernel_launch(void* const* d_in, const int* in_sizes, int n_in,
                              void* d_out, int out_size)
{
    const float* query  = (const float*)d_in[0];
    const float* key    = (const float*)d_in[1];
    const float* values = (const float*)d_in[2];
    const float* Wk     = (const float*)d_in[3];
    const float* bk     = (const float*)d_in[4];
    const float* Wv     = (const float*)d_in[5];
    const float* bv     = (const float*)d_in[6];
    const float* Wo     = (const float*)d_in[7];
    const float* bo     = (const float*)d_in[8];
    const float* gammas = (const float*)d_in[9];
    const float* ln1_g  = (const float*)d_in[10];
    const float* ln1_b  = (const float*)d_in[11];
    const float* W1     = (const float*)d_in[12];
    const float* b1     = (const float*)d_in[13];
    const float* W2     = (const float*)d_in[14];
    const float* b2     = (const float*)d_in[15];
    const float* ln2_g  = (const float*)d_in[16];
    const float* ln2_b  = (const float*)d_in[17];
    float* out = (float*)d_out;

    float *ao, *x1, *f2;
    __half *in16q, *in16k, *in16v, *qh, *kh, *vh, *ctx16, *x116, *h116;
    __half *wkT16, *wvT16, *woT16, *w1T16, *w2T16;
    cudaGetSymbolAddress((void**)&ao,  g_ao);
    cudaGetSymbolAddress((void**)&x1,  g_x1);
    cudaGetSymbolAddress((void**)&f2,  g_f2);
    cudaGetSymbolAddress((void**)&in16q, g_in16q);
    cudaGetSymbolAddress((void**)&in16k, g_in16k);
    cudaGetSymbolAddress((void**)&in16v, g_in16v);
    cudaGetSymbolAddress((void**)&qh,  g_qh);
    cudaGetSymbolAddress((void**)&kh,  g_kh);
    cudaGetSymbolAddress((void**)&vh,  g_vh);
    cudaGetSymbolAddress((void**)&ctx16, g_ctx16);
    cudaGetSymbolAddress((void**)&x116,  g_x116);
    cudaGetSymbolAddress((void**)&h116,  g_h116);
    cudaGetSymbolAddress((void**)&wkT16, g_wkT16);
    cudaGetSymbolAddress((void**)&wvT16, g_wvT16);
    cudaGetSymbolAddress((void**)&woT16, g_woT16);
    cudaGetSymbolAddress((void**)&w1T16, g_w1T16);
    cudaGetSymbolAddress((void**)&w2T16, g_w2T16);

    cudaFuncSetAttribute(attn_mma, cudaFuncAttributeMaxDynamicSharedMemorySize, ATTN_SMEM);
    cudaFuncSetAttribute(gemm_h<false,false>, cudaFuncAttributeMaxDynamicSharedMemorySize, GEMM_H_SMEM);
    cudaFuncSetAttribute(gemm_h<true, true >, cudaFuncAttributeMaxDynamicSharedMemorySize, GEMM_H_SMEM);
    cudaFuncSetAttribute(gemm_proj3_h, cudaFuncAttributeMaxDynamicSharedMemorySize, GEMM_H_SMEM);

    // ---- prep (single launch) ----
    prep_all<<<dim3(64, 64, 8), 256>>>(query, key, values, in16q, in16k, in16v,
                                       Wk, Wv, Wo, W1, W2,
                                       wkT16, wvT16, woT16, w1T16, w2T16);

    const dim3 gProj (DD / 64,   MROWS / 128);      // (8, 64)
    const dim3 gProj3(DD / 64,   MROWS / 128, 3);
    const dim3 gFF1  (DFFN / 64, MROWS / 128);      // (32, 64)

    gemm_proj3_h<<<gProj3, 128, GEMM_H_SMEM>>>(in16q, in16k, in16v, wkT16, wvT16,
                                               bk, bv, qh, kh, vh);

    attn_mma<<<dim3(SS / TQ, HH, BB), 512, ATTN_SMEM>>>(qh, kh, vh, gammas, ctx16);

    gemm_h<false,false><<<gProj, 128, GEMM_H_SMEM>>>(ctx16, woT16, bo, ao, (__half*)0,
                                                     MROWS, DD, DD);

    add_ln<<<MROWS / 8, 256>>>(query, ao, ln1_g, ln1_b, x1, x116);

    gemm_h<true, true ><<<gFF1, 128, GEMM_H_SMEM>>>(x116, w1T16, b1, (float*)0, h116,
                                                    MROWS, DFFN, DD);
    gemm_h<false,false><<<gProj, 128, GEMM_H_SMEM>>>(h116, w2T16, b2, f2, (__half*)0,
                                                     MROWS, DD, DFFN);

    add_ln<<<MROWS / 8, 256>>>(x1, f2, ln2_g, ln2_b, out, (__half*)0);
}

// round 17
// speedup vs baseline: 1.0493x; 1.0493x over previous
#include <cuda_runtime.h>
#include <cuda_fp16.h>
#include <cstdint>
#include <math.h>

// Problem constants
#define BB   16
#define SS   512
#define DD   512
#define HH   8
#define DK   64
#define DFFN 2048
#define MROWS (BB*SS)   // 8192

// ---------------- scratch (static device globals; no allocation) ----------------
__device__ float g_ao [MROWS*DD];
__device__ float g_x1 [MROWS*DD];
__device__ float g_f2 [MROWS*DD];
__device__ __half g_qh  [MROWS*DD];
__device__ __half g_kh  [MROWS*DD];
__device__ __half g_vh  [MROWS*DD];
__device__ __half g_ctx16[MROWS*DD];
__device__ __half g_x116 [MROWS*DD];
__device__ __half g_h116 [MROWS*DFFN];
__device__ __half g_wkT16[DD*DD];
__device__ __half g_wvT16[DD*DD];
__device__ __half g_woT16[DD*DD];
__device__ __half g_w1T16[DFFN*DD];
__device__ __half g_w2T16[DD*DFFN];

// ---------------- helpers ----------------
__device__ __forceinline__ uint32_t smem_to_u32(const void* p) {
    uint32_t a;
    asm("{ .reg .u64 tmp; cvta.to.shared.u64 tmp, %1; cvt.u32.u64 %0, tmp; }" : "=r"(a) : "l"(p));
    return a;
}
#define CP_ASYNC16(saddr, gptr) \
    asm volatile("cp.async.cg.shared.global [%0], [%1], 16;" :: "r"(saddr), "l"(gptr))
#define CP_COMMIT() asm volatile("cp.async.commit_group;" ::: "memory")
#define CP_WAIT0()  asm volatile("cp.async.wait_group 0;" ::: "memory")
#define CP_WAIT1()  asm volatile("cp.async.wait_group 1;" ::: "memory")

__device__ __forceinline__ void mma_f16(float* c, const uint32_t* a, const uint32_t* b) {
    asm volatile(
        "mma.sync.aligned.m16n8k16.row.col.f32.f16.f16.f32 "
        "{%0,%1,%2,%3}, {%4,%5,%6,%7}, {%8,%9}, {%0,%1,%2,%3};"
        : "+f"(c[0]), "+f"(c[1]), "+f"(c[2]), "+f"(c[3])
        : "r"(a[0]), "r"(a[1]), "r"(a[2]), "r"(a[3]), "r"(b[0]), "r"(b[1]));
}
__device__ __forceinline__ void ldmx4(uint32_t* r, uint32_t addr) {
    asm volatile("ldmatrix.sync.aligned.m8n8.x4.shared.b16 {%0,%1,%2,%3}, [%4];"
                 : "=r"(r[0]), "=r"(r[1]), "=r"(r[2]), "=r"(r[3]) : "r"(addr));
}
__device__ __forceinline__ void ldmx2_trans(uint32_t& r0, uint32_t& r1, uint32_t addr) {
    asm volatile("ldmatrix.sync.aligned.m8n8.x2.trans.shared.b16 {%0,%1}, [%2];"
                 : "=r"(r0), "=r"(r1) : "r"(addr));
}

__device__ __forceinline__ float fexp(float x) {
    float y;
    asm("ex2.approx.f32 %0, %1;" : "=f"(y) : "f"(x * 1.4426950408889634f));
    return y;
}
__device__ __forceinline__ float fsqrt_ap(float x) {
    float y;
    asm("sqrt.approx.f32 %0, %1;" : "=f"(y) : "f"(x));
    return y;
}

// ========================= fp16 mma GEMM (128x128, 256 thr, 2-stage, 2 CTA/SM) =========================
#define HP 72
#define TILE_H (128*HP)
#define STAGE_H (2*TILE_H)
#define GEMM_H_SMEM (2*STAGE_H*(int)sizeof(__half))   // 73,728 B

__device__ __forceinline__ void fill_A16(const __half* __restrict__ A, int K,
                                         int bm, int kc, uint32_t sA, int t)
{
#pragma unroll
    for (int i = 0; i < 4; i++) {
        int id = t + i * 256;
        int row = id >> 3, c = id & 7;
        CP_ASYNC16(sA + (uint32_t)(row * HP + c * 8) * 2u,
                   A + (size_t)(bm + row) * K + kc * 64 + c * 8);
    }
}
__device__ __forceinline__ void fill_B16(const __half* __restrict__ Bt, int K,
                                         int bn, int kc, uint32_t sB, int t)
{
#pragma unroll
    for (int i = 0; i < 4; i++) {
        int id = t + i * 256;
        int row = id >> 3, c = id & 7;
        CP_ASYNC16(sB + (uint32_t)(row * HP + c * 8) * 2u,
                   Bt + (size_t)(bn + row) * K + kc * 64 + c * 8);
    }
}
// A fill from fp32 (LDG + cvt + STS); used by projection GEMM
__device__ __forceinline__ void fill_A32(const float* __restrict__ A, int K,
                                         int bm, int kc, uint32_t sA, int t)
{
#pragma unroll
    for (int i = 0; i < 8; i++) {
        int id = t + i * 256;
        int row = id >> 4, c4 = id & 15;
        float4 v = *(const float4*)(A + (size_t)(bm + row) * K + kc * 64 + c4 * 4);
        __half2 h0 = __floats2half2_rn(v.x, v.y);
        __half2 h1 = __floats2half2_rn(v.z, v.w);
        asm volatile("st.shared.v2.b32 [%0], {%1,%2};"
                     :: "r"(sA + (uint32_t)(row * HP + c4 * 4) * 2u),
                        "r"(*(uint32_t*)&h0), "r"(*(uint32_t*)&h1) : "memory");
    }
}

// shared compute for one k-chunk (reads aSa/bSa, accumulates)
__device__ __forceinline__ void gemm_chunk(float acc[4][4][4], uint32_t aSa, uint32_t bSa,
                                           int wm, int wn, int rowA, int colA,
                                           int rowB, int colB)
{
#pragma unroll
    for (int ks = 0; ks < 4; ks++) {
        const int k0 = ks * 16;
        uint32_t af[4][4];
#pragma unroll
        for (int mt = 0; mt < 4; mt++)
            ldmx4(af[mt], aSa + (uint32_t)((wm + mt * 16 + rowA) * HP + k0 + colA) * 2u);
        uint32_t bf[4][2];
#pragma unroll
        for (int nh = 0; nh < 2; nh++) {
            uint32_t b4[4];
            ldmx4(b4, bSa + (uint32_t)((wn + nh * 16 + rowB) * HP + k0 + colB) * 2u);
            bf[2*nh  ][0] = b4[0]; bf[2*nh  ][1] = b4[1];
            bf[2*nh+1][0] = b4[2]; bf[2*nh+1][1] = b4[3];
        }
#pragma unroll
        for (int mt = 0; mt < 4; mt++)
#pragma unroll
            for (int nt = 0; nt < 4; nt++)
                mma_f16(acc[mt][nt], af[mt], bf[nt]);
    }
}

template<bool RELU, bool OUT16>
__device__ __forceinline__ void gemm_epilogue(float acc[4][4][4],
                                              const float* __restrict__ bias,
                                              float* __restrict__ C, __half* __restrict__ C16,
                                              int N, int bm, int bn, int wm, int wn,
                                              int g, int tg)
{
#pragma unroll
    for (int mt = 0; mt < 4; mt++) {
#pragma unroll
        for (int nt = 0; nt < 4; nt++) {
            const int row0 = bm + wm + mt * 16 + g;
            const int col  = bn + wn + nt * 8 + 2 * tg;
            float b0 = bias[col], b1 = bias[col + 1];
            float v0 = acc[mt][nt][0] + b0, v1 = acc[mt][nt][1] + b1;
            float v2 = acc[mt][nt][2] + b0, v3 = acc[mt][nt][3] + b1;
            if (RELU) {
                v0 = fmaxf(v0, 0.f); v1 = fmaxf(v1, 0.f);
                v2 = fmaxf(v2, 0.f); v3 = fmaxf(v3, 0.f);
            }
            if (OUT16) {
                *(__half2*)(C16 + (size_t)row0 * N + col)       = __floats2half2_rn(v0, v1);
                *(__half2*)(C16 + (size_t)(row0 + 8) * N + col) = __floats2half2_rn(v2, v3);
            } else {
                *(float2*)(C + (size_t)row0 * N + col)       = make_float2(v0, v1);
                *(float2*)(C + (size_t)(row0 + 8) * N + col) = make_float2(v2, v3);
            }
        }
    }
}

template<bool RELU, bool OUT16>
__global__ __launch_bounds__(256, 2)
void gemm_h(const __half* __restrict__ A, const __half* __restrict__ Bt,
            const float* __restrict__ bias, float* __restrict__ C,
            __half* __restrict__ C16, int M, int N, int K)
{
    extern __shared__ __align__(16) __half smem_h[];
    const int t    = threadIdx.x;
    const int lane = t & 31, wid = t >> 5;
    const int g    = lane >> 2, tg = lane & 3;
    const int wm   = (wid >> 2) * 64;
    const int wn   = (wid & 3) * 32;
    const int r8   = lane & 7, quad = lane >> 3;
    const int rowA = (quad & 1) * 8 + r8, colA = (quad >> 1) * 8;
    const int rowB = (quad >> 1) * 8 + r8, colB = (quad & 1) * 8;
    const int bm = blockIdx.y * 128, bn = blockIdx.x * 128;
    const uint32_t sbase = smem_to_u32(smem_h);

    float acc[4][4][4];
#pragma unroll
    for (int mt = 0; mt < 4; mt++)
#pragma unroll
        for (int nt = 0; nt < 4; nt++)
#pragma unroll
            for (int r = 0; r < 4; r++) acc[mt][nt][r] = 0.f;

    const int nk = K >> 6;

    fill_A16(A, K, bm, 0, sbase, t);
    fill_B16(Bt, K, bn, 0, sbase + TILE_H * 2, t);
    CP_COMMIT();

    for (int kc = 0; kc < nk; kc++) {
        CP_WAIT0();
        __syncthreads();
        if (kc + 1 < nk) {
            const uint32_t off = ((kc + 1) & 1) * (uint32_t)(STAGE_H * 2);
            fill_A16(A, K, bm, kc + 1, sbase + off, t);
            fill_B16(Bt, K, bn, kc + 1, sbase + off + TILE_H * 2, t);
            CP_COMMIT();
        }
        const uint32_t aSa = sbase + (uint32_t)((kc & 1) * STAGE_H) * 2u;
        gemm_chunk(acc, aSa, aSa + (uint32_t)TILE_H * 2u, wm, wn, rowA, colA, rowB, colB);
    }
    gemm_epilogue<RELU, OUT16>(acc, bias, C, C16, N, bm, bn, wm, wn, g, tg);
}

// batched q/k/v projections: A is fp32 (conversion fused into fill)
__global__ __launch_bounds__(256, 2)
void gemm_proj3_f(const float* __restrict__ A0, const float* __restrict__ A1,
                  const float* __restrict__ A2,
                  const __half* __restrict__ WkT, const __half* __restrict__ WvT,
                  const float* __restrict__ bk, const float* __restrict__ bv,
                  __half* __restrict__ C0, __half* __restrict__ C1, __half* __restrict__ C2)
{
    extern __shared__ __align__(16) __half smem_h[];
    const int z = blockIdx.z;
    const float* A = (z == 0) ? A0 : (z == 1) ? A1 : A2;
    const __half* Bt = (z == 2) ? WvT : WkT;
    const float* bias = (z == 2) ? bv : bk;
    __half* C16 = (z == 0) ? C0 : (z == 1) ? C1 : C2;

    const int t    = threadIdx.x;
    const int lane = t & 31, wid = t >> 5;
    const int g    = lane >> 2, tg = lane & 3;
    const int wm   = (wid >> 2) * 64;
    const int wn   = (wid & 3) * 32;
    const int r8   = lane & 7, quad = lane >> 3;
    const int rowA = (quad & 1) * 8 + r8, colA = (quad >> 1) * 8;
    const int rowB = (quad >> 1) * 8 + r8, colB = (quad & 1) * 8;
    const int bm = blockIdx.y * 128, bn = blockIdx.x * 128;
    const uint32_t sbase = smem_to_u32(smem_h);

    float acc[4][4][4];
#pragma unroll
    for (int mt = 0; mt < 4; mt++)
#pragma unroll
        for (int nt = 0; nt < 4; nt++)
#pragma unroll
            for (int r = 0; r < 4; r++) acc[mt][nt][r] = 0.f;

    const int nk = DD >> 6;    // 8

    // prologue: A0 via LDG/STS, B0 via cp.async
    fill_A32(A, DD, bm, 0, sbase, t);
    fill_B16(Bt, DD, bn, 0, sbase + TILE_H * 2, t);
    CP_COMMIT();

    for (int kc = 0; kc < nk; kc++) {
        CP_WAIT0();              // B(kc) landed
        __syncthreads();         // publishes A(kc) STS + retires all reads of buf^1
        const uint32_t off1 = ((kc + 1) & 1) * (uint32_t)(STAGE_H * 2);
        if (kc + 1 < nk) {
            fill_B16(Bt, DD, bn, kc + 1, sbase + off1 + TILE_H * 2, t);
            CP_COMMIT();
        }
        const uint32_t aSa = sbase + (uint32_t)((kc & 1) * STAGE_H) * 2u;
        gemm_chunk(acc, aSa, aSa + (uint32_t)TILE_H * 2u, wm, wn, rowA, colA, rowB, colB);
        if (kc + 1 < nk)
            fill_A32(A, DD, bm, kc + 1, sbase + off1, t);  // LDG overlaps other warps' mma
    }
    gemm_epilogue<false, true>(acc, bias, (float*)0, C16, DD, bm, bn, wm, wn, g, tg);
}

// ---------------- prep: weight transposes only ----------------
__global__ __launch_bounds__(256)
void prep_all(const float* __restrict__ Wk, const float* __restrict__ Wv,
              const float* __restrict__ Wo, const float* __restrict__ W1,
              const float* __restrict__ W2,
              __half* __restrict__ o0, __half* __restrict__ o1,
              __half* __restrict__ o2, __half* __restrict__ o3,
              __half* __restrict__ o4)
{
    const int z = blockIdx.z;
    const float* in; __half* out; int R, C;
    switch (z) {
        case 0: in = Wk; out = o0; R = DD;   C = DD;   break;
        case 1: in = Wv; out = o1; R = DD;   C = DD;   break;
        case 2: in = Wo; out = o2; R = DD;   C = DD;   break;
        case 3: in = W1; out = o3; R = DD;   C = DFFN; break;
        default:in = W2; out = o4; R = DFFN; C = DD;   break;
    }
    const int bx = blockIdx.x * 32;
    const int by = blockIdx.y * 32;
    if (bx >= C || by >= R) return;
    __shared__ float tile[32][33];
    const int tx = threadIdx.x & 31;
    const int ty = threadIdx.x >> 5;
#pragma unroll
    for (int i = 0; i < 32; i += 8)
        tile[ty + i][tx] = in[(size_t)(by + ty + i) * C + bx + tx];
    __syncthreads();
#pragma unroll
    for (int i = 0; i < 32; i += 8)
        out[(size_t)(bx + ty + i) * R + by + tx] = __float2half(tile[tx][ty + i]);
}

// ========================= Fused AKT attention: TQ=32, 512 thr, fp16 scores =========================
#define TQ   32
#define CH   128
#define PP   520
#define QP   72
#define KVP  72
#define KVBUF (128*KVP)
#define OFF_Q   33280
#define OFF_KV  (33280+4608)
#define ATTN_SMEM (33280+4608+36864)     // 74,752 B -> 2 CTAs/SM

template<int NCH>
__device__ __forceinline__ void phase_b(__half* sRawH, int w, int lane,
                                        int i0, float gamma)
{
    constexpr int VN = 4 * NCH;
#pragma unroll
    for (int rr2 = 0; rr2 < 2; rr2++) {
        const int row_i = w + rr2 * 16;
        const int ig = i0 + row_i;
        const uint32_t* rp = (const uint32_t*)(sRawH + row_i * PP) + lane * (VN / 2);

        float vals[VN];
#pragma unroll
        for (int u = 0; u < VN / 2; u++) {
            float2 f2 = __half22float2(*(const __half2*)(rp + u));
            vals[2*u] = f2.x; vals[2*u+1] = f2.y;
        }

        float mx = -1e32f;
#pragma unroll
        for (int m = 0; m < VN; m++) mx = fmaxf(mx, vals[m]);
#pragma unroll
        for (int off = 16; off > 0; off >>= 1) mx = fmaxf(mx, __shfl_xor_sync(0xffffffffu, mx, off));

        float p[VN]; float s = 0.f;
#pragma unroll
        for (int m = 0; m < VN; m++) { p[m] = fexp(vals[m] - mx); s += p[m]; }
#pragma unroll
        for (int off = 16; off > 0; off >>= 1) s += __shfl_xor_sync(0xffffffffu, s, off);
        const float inv = 1.f / s;

        float local = 0.f; float cum[VN];
#pragma unroll
        for (int m = 0; m < VN; m++) { local += p[m] * inv; cum[m] = local; }
        float run = local;
#pragma unroll
        for (int off = 1; off < 32; off <<= 1) {
            float vv = __shfl_up_sync(0xffffffffu, run, off);
            if (lane >= off) run += vv;
        }
        const float prefix = run - local;
        const float total  = __shfl_sync(0xffffffffu, run, 31);

#pragma unroll
        for (int m = 0; m < VN; m++) {
            int jg = lane * VN + m;
            float suffix = fmaxf(total - (prefix + cum[m]), 0.f);
            float pe = fabsf((float)(ig - jg));
            float dist = fsqrt_ap(suffix * pe);
            float eff = fexp(dist * gamma);
            eff = fminf(fmaxf(eff, 1e-5f), 1e5f);
            vals[m] = vals[m] * eff;
        }

        float mx2 = -1e32f;
#pragma unroll
        for (int m = 0; m < VN; m++) mx2 = fmaxf(mx2, vals[m]);
#pragma unroll
        for (int off = 16; off > 0; off >>= 1) mx2 = fmaxf(mx2, __shfl_xor_sync(0xffffffffu, mx2, off));
        float s2 = 0.f;
#pragma unroll
        for (int m = 0; m < VN; m++) { vals[m] = fexp(vals[m] - mx2); s2 += vals[m]; }
#pragma unroll
        for (int off = 16; off > 0; off >>= 1) s2 += __shfl_xor_sync(0xffffffffu, s2, off);
        const float inv2 = 1.f / s2;

        uint32_t* wp = (uint32_t*)(sRawH + row_i * PP) + lane * (VN / 2);
#pragma unroll
        for (int u = 0; u < VN / 2; u++) {
            __half2 hv = __floats2half2_rn(vals[2*u] * inv2, vals[2*u+1] * inv2);
            *(__half2*)(wp + u) = hv;
        }
    }
}

__global__ __launch_bounds__(512, 2)
void attn_mma(const __half* __restrict__ Q, const __half* __restrict__ K,
              const __half* __restrict__ V, const float* __restrict__ gammas,
              __half* __restrict__ CTX16)
{
    extern __shared__ __align__(16) char smem_c[];
    __half* sRawH = (__half*)smem_c;
    __half* sQ    = (__half*)(smem_c + OFF_Q);
    __half* sKV   = (__half*)(smem_c + OFF_KV);
    const uint32_t sRa  = smem_to_u32(sRawH);
    const uint32_t sQa  = smem_to_u32(sQ);
    const uint32_t sKVa = smem_to_u32(sKV);

    const int t    = threadIdx.x;
    const int lane = t & 31, w = t >> 5;
    const int g    = lane >> 2, tg = lane & 3;
    const int r8   = lane & 7, quad = lane >> 3;
    const int rowA = (quad & 1) * 8 + r8, colA = (quad >> 1) * 8;
    const int rowB = (quad >> 1) * 8 + r8, colB = (quad & 1) * 8;
    const int qt = (int)(gridDim.x - 1 - blockIdx.x);
    const int h = blockIdx.y, b = blockIdx.z;
    const int i0 = qt * TQ;
    const int nch = (i0 + TQ + CH - 1) >> 7;

    if (t < 256) {
        int r = t >> 3, c8 = t & 7;
        CP_ASYNC16(sQa + (uint32_t)(r * QP + c8 * 8) * 2u,
                   Q + (size_t)(b * SS + i0 + r) * DD + h * 64 + c8 * 8);
    }
    CP_COMMIT();
    {
        const __half* Kb = K + (size_t)(b * SS) * DD + h * 64;
#pragma unroll
        for (int i = 0; i < 2; i++) {
            int id = t + i * 512;
            int r = id >> 3, c8 = id & 7;
            CP_ASYNC16(sKVa + (uint32_t)(r * KVP + c8 * 8) * 2u,
                       Kb + (size_t)r * DD + c8 * 8);
        }
    }
    CP_COMMIT();

    const int rgA = w >> 3;
    const int jsl = (w & 7) * 16;

    CP_WAIT1();
    __syncthreads();
    uint32_t qf[4][4];
#pragma unroll
    for (int ks = 0; ks < 4; ks++)
        ldmx4(qf[ks], sQa + (uint32_t)((rgA * 16 + rowA) * QP + ks * 16 + colA) * 2u);

    const int imax_rg = i0 + rgA * 16 + 15;
    for (int c = 0; c < nch; c++) {
        CP_WAIT0();
        __syncthreads();
        if (c + 1 < nch) {
            const __half* Kb = K + (size_t)(b * SS + (c + 1) * CH) * DD + h * 64;
            const uint32_t dst = sKVa + (uint32_t)(((c + 1) & 1) * KVBUF) * 2u;
#pragma unroll
            for (int i = 0; i < 2; i++) {
                int id = t + i * 512;
                int r = id >> 3, c8 = id & 7;
                CP_ASYNC16(dst + (uint32_t)(r * KVP + c8 * 8) * 2u,
                           Kb + (size_t)r * DD + c8 * 8);
            }
            CP_COMMIT();
        }

        const int rr = rgA * 16 + g;
        if (c * CH + jsl > imax_rg) {
            const __half2 ninf = __floats2half2_rn(-1e30f, -1e30f);
#pragma unroll
            for (int nt = 0; nt < 2; nt++) {
                const int j = c * CH + jsl + nt * 8 + 2 * tg;
                *(__half2*)(sRawH + (rr    ) * PP + j) = ninf;
                *(__half2*)(sRawH + (rr + 8) * PP + j) = ninf;
            }
            continue;
        }

        const uint32_t kba = sKVa + (uint32_t)((c & 1) * KVBUF) * 2u;
        float acc[2][4] = {{0.f,0.f,0.f,0.f},{0.f,0.f,0.f,0.f}};
#pragma unroll
        for (int ks = 0; ks < 4; ks++) {
            uint32_t b4[4];
            ldmx4(b4, kba + (uint32_t)((jsl + rowB) * KVP + ks * 16 + colB) * 2u);
            mma_f16(acc[0], qf[ks], b4 + 0);
            mma_f16(acc[1], qf[ks], b4 + 2);
        }
        const int ilo = i0 + rr, ihi = i0 + rr + 8;
#pragma unroll
        for (int nt = 0; nt < 2; nt++) {
            const int j = c * CH + jsl + nt * 8 + 2 * tg;
            float v0 = (j     <= ilo) ? acc[nt][0] * 0.125f : -1e30f;
            float v1 = (j + 1 <= ilo) ? acc[nt][1] * 0.125f : -1e30f;
            float v2 = (j     <= ihi) ? acc[nt][2] * 0.125f : -1e30f;
            float v3 = (j + 1 <= ihi) ? acc[nt][3] * 0.125f : -1e30f;
            *(__half2*)(sRawH + (rr    ) * PP + j) = __floats2half2_rn(v0, v1);
            *(__half2*)(sRawH + (rr + 8) * PP + j) = __floats2half2_rn(v2, v3);
        }
    }
    __syncthreads();

    {
        const __half* Vb = V + (size_t)(b * SS) * DD + h * 64;
#pragma unroll
        for (int i = 0; i < 2; i++) {
            int id = t + i * 512;
            int r = id >> 3, c8 = id & 7;
            CP_ASYNC16(sKVa + (uint32_t)(r * KVP + c8 * 8) * 2u,
                       Vb + (size_t)r * DD + c8 * 8);
        }
    }
    CP_COMMIT();

    {
        float gm  = gammas[h];
        float sp  = (gm > 20.f) ? gm : log1pf(expf(gm));
        float gamma = -sp;
        switch (nch) {
            case 1:  phase_b<1>(sRawH, w, lane, i0, gamma); break;
            case 2:  phase_b<2>(sRawH, w, lane, i0, gamma); break;
            case 3:  phase_b<3>(sRawH, w, lane, i0, gamma); break;
            default: phase_b<4>(sRawH, w, lane, i0, gamma); break;
        }
    }
    __syncthreads();

    float oc[4] = {0.f, 0.f, 0.f, 0.f};
    const int rgC  = w >> 3;
    const int dcol = (w & 7) * 8;
    const int lrow = lane & 15;
    const int jlim = i0 + TQ;
    for (int c = 0; c < nch; c++) {
        CP_WAIT0();
        __syncthreads();
        if (c + 1 < nch) {
            const __half* Vb = V + (size_t)(b * SS + (c + 1) * CH) * DD + h * 64;
            const uint32_t dst = sKVa + (uint32_t)(((c + 1) & 1) * KVBUF) * 2u;
#pragma unroll
            for (int i = 0; i < 2; i++) {
                int id = t + i * 512;
                int r = id >> 3, c8 = id & 7;
                CP_ASYNC16(dst + (uint32_t)(r * KVP + c8 * 8) * 2u,
                           Vb + (size_t)r * DD + c8 * 8);
            }
            CP_COMMIT();
        }
        const uint32_t vba = sKVa + (uint32_t)((c & 1) * KVBUF) * 2u;

        const int kmax = (jlim - c * CH < CH) ? (jlim - c * CH) : CH;
        for (int kk = 0; kk < kmax; kk += 16) {
            const int jcol = c * CH + kk;
            uint32_t af[4];
            ldmx4(af, sRa + (uint32_t)((rgC * 16 + rowA) * PP + jcol + colA) * 2u);
            uint32_t bf[2];
            ldmx2_trans(bf[0], bf[1],
                        vba + (uint32_t)((kk + lrow) * KVP + dcol) * 2u);
            mma_f16(oc, af, bf);
        }
    }

    const int row0 = i0 + rgC * 16 + g;
    const int col  = h * 64 + dcol + 2 * tg;
    *(__half2*)(CTX16 + (size_t)(b * SS + row0    ) * DD + col) = __floats2half2_rn(oc[0], oc[1]);
    *(__half2*)(CTX16 + (size_t)(b * SS + row0 + 8) * DD + col) = __floats2half2_rn(oc[2], oc[3]);
}

// ---------------- residual add + LayerNorm: warp per row ----------------
__global__ __launch_bounds__(256)
void add_ln(const float* __restrict__ A, const float* __restrict__ B,
            const float* __restrict__ g, const float* __restrict__ be,
            float* __restrict__ O, __half* __restrict__ O16)
{
    const int lane = threadIdx.x & 31;
    const int row  = blockIdx.x * 8 + (threadIdx.x >> 5);
    const float4* a4 = (const float4*)(A + (size_t)row * DD);
    const float4* b4 = (const float4*)(B + (size_t)row * DD);
    const float4* g4 = (const float4*)g;
    const float4* e4 = (const float4*)be;

    float4 x[4];
    float s = 0.f, sq = 0.f;
#pragma unroll
    for (int u = 0; u < 4; u++) {
        const int idx = lane + 32 * u;
        float4 av = a4[idx], bv = b4[idx];
        x[u].x = av.x + bv.x; x[u].y = av.y + bv.y;
        x[u].z = av.z + bv.z; x[u].w = av.w + bv.w;
        s  += x[u].x + x[u].y + x[u].z + x[u].w;
        sq += x[u].x * x[u].x + x[u].y * x[u].y + x[u].z * x[u].z + x[u].w * x[u].w;
    }
#pragma unroll
    for (int off = 16; off > 0; off >>= 1) {
        s  += __shfl_xor_sync(0xffffffffu, s, off);
        sq += __shfl_xor_sync(0xffffffffu, sq, off);
    }
    const float mu   = s * (1.f / 512.f);
    const float var  = fmaxf(sq * (1.f / 512.f) - mu * mu, 0.f);
    const float rstd = rsqrtf(var + 1e-5f);

    float4* o4 = (float4*)(O + (size_t)row * DD);
#pragma unroll
    for (int u = 0; u < 4; u++) {
        const int idx = lane + 32 * u;
        float4 gv = g4[idx], ev = e4[idx];
        float4 y;
        y.x = (x[u].x - mu) * rstd * gv.x + ev.x;
        y.y = (x[u].y - mu) * rstd * gv.y + ev.y;
        y.z = (x[u].z - mu) * rstd * gv.z + ev.z;
        y.w = (x[u].w - mu) * rstd * gv.w + ev.w;
        o4[idx] = y;
        if (O16) {
            __half2* h2 = (__half2*)(O16 + (size_t)row * DD + idx * 4);
            h2[0] = __floats2half2_rn(y.x, y.y);
            h2[1] = __floats2half2_rn(y.z, y.w);
        }
    }
}

// ---------------- launch ----------------
extern "C" void kernel_launch(void* const* d_in, const int* in_sizes, int n_in,
                              void* d_out, int out_size)
{
    const float* query  = (const float*)d_in[0];
    const float* key    = (const float*)d_in[1];
    const float* values = (const float*)d_in[2];
    const float* Wk     = (const float*)d_in[3];
    const float* bk     = (const float*)d_in[4];
    const float* Wv     = (const float*)d_in[5];
    const float* bv     = (const float*)d_in[6];
    const float* Wo     = (const float*)d_in[7];
    const float* bo     = (const float*)d_in[8];
    const float* gammas = (const float*)d_in[9];
    const float* ln1_g  = (const float*)d_in[10];
    const float* ln1_b  = (const float*)d_in[11];
    const float* W1     = (const float*)d_in[12];
    const float* b1     = (const float*)d_in[13];
    const float* W2     = (const float*)d_in[14];
    const float* b2     = (const float*)d_in[15];
    const float* ln2_g  = (const float*)d_in[16];
    const float* ln2_b  = (const float*)d_in[17];
    float* out = (float*)d_out;

    float *ao, *x1, *f2;
    __half *qh, *kh, *vh, *ctx16, *x116, *h116;
    __half *wkT16, *wvT16, *woT16, *w1T16, *w2T16;
    cudaGetSymbolAddress((void**)&ao,  g_ao);
    cudaGetSymbolAddress((void**)&x1,  g_x1);
    cudaGetSymbolAddress((void**)&f2,  g_f2);
    cudaGetSymbolAddress((void**)&qh,  g_qh);
    cudaGetSymbolAddress((void**)&kh,  g_kh);
    cudaGetSymbolAddress((void**)&vh,  g_vh);
    cudaGetSymbolAddress((void**)&ctx16, g_ctx16);
    cudaGetSymbolAddress((void**)&x116,  g_x116);
    cudaGetSymbolAddress((void**)&h116,  g_h116);
    cudaGetSymbolAddress((void**)&wkT16, g_wkT16);
    cudaGetSymbolAddress((void**)&wvT16, g_wvT16);
    cudaGetSymbolAddress((void**)&woT16, g_woT16);
    cudaGetSymbolAddress((void**)&w1T16, g_w1T16);
    cudaGetSymbolAddress((void**)&w2T16, g_w2T16);

    cudaFuncSetAttribute(attn_mma, cudaFuncAttributeMaxDynamicSharedMemorySize, ATTN_SMEM);
    cudaFuncSetAttribute(gemm_h<false,false>, cudaFuncAttributeMaxDynamicSharedMemorySize, GEMM_H_SMEM);
    cudaFuncSetAttribute(gemm_h<true, true >, cudaFuncAttributeMaxDynamicSharedMemorySize, GEMM_H_SMEM);
    cudaFuncSetAttribute(gemm_proj3_f, cudaFuncAttributeMaxDynamicSharedMemorySize, GEMM_H_SMEM);

    // ---- prep: weight transposes (single launch) ----
    prep_all<<<dim3(64, 64, 5), 256>>>(Wk, Wv, Wo, W1, W2,
                                       wkT16, wvT16, woT16, w1T16, w2T16);

    const dim3 gProj (DD / 128,   MROWS / 128);     // (4, 64)
    const dim3 gProj3(DD / 128,   MROWS / 128, 3);
    const dim3 gFF1  (DFFN / 128, MROWS / 128);     // (16, 64)

    // projections: fp32 inputs, conversion fused into A-fill
    gemm_proj3_f<<<gProj3, 256, GEMM_H_SMEM>>>(query, key, values, wkT16, wvT16,
                                               bk, bv, qh, kh, vh);

    attn_mma<<<dim3(SS / TQ, HH, BB), 512, ATTN_SMEM>>>(qh, kh, vh, gammas, ctx16);

    gemm_h<false,false><<<gProj, 256, GEMM_H_SMEM>>>(ctx16, woT16, bo, ao, (__half*)0,
                                                     MROWS, DD, DD);

    add_ln<<<MROWS / 8, 256>>>(query, ao, ln1_g, ln1_b, x1, x116);

    gemm_h<true, true ><<<gFF1, 256, GEMM_H_SMEM>>>(x116, w1T16, b1, (float*)0, h116,
                                                    MROWS, DFFN, DD);
    gemm_h<false,false><<<gProj, 256, GEMM_H_SMEM>>>(h116, w2T16, b2, f2, (__half*)0,
                                                     MROWS, DD, DFFN);

    add_ln<<<MROWS / 8, 256>>>(x1, f2, ln2_g, ln2_b, out, (__half*)0);
}